// round 1
// baseline (speedup 1.0000x reference)
#include <cuda_runtime.h>
#include <cstdint>

#define Hdim 768
#define Mdim 36
#define KC 128
#define CHUNKS 6            // 768/128
#define T1 288
#define NP1 1369            // 37*37

// ---------------- smem offsets for kernel 1 (in floats) ----------------
#define OXS 0               // x tiles: 2 bufs * 36 rows * 132 stride = 9504
#define OYS 9504            // y tiles: 9504
#define OGW 19008           // g*w vector: 768
#define OCS 19776           // couplings 37*37 = 1369
#define OST 21145           // stat partials 72*4*3 = 864
#define ORN 22009           // rsqrt row norms, 72
#define ODU 22081           // dustbin scores*10, 72
#define OWP 22153           // warp partials 9*2 = 18
#define SM1_FLOATS 22176
#define SM1_BYTES (SM1_FLOATS*4)

__device__ __forceinline__ void fma2(unsigned long long &d,
                                     unsigned long long a,
                                     unsigned long long b) {
    asm volatile("fma.rn.f32x2 %0, %1, %2, %0;" : "+l"(d) : "l"(a), "l"(b));
}

__device__ __forceinline__ void cp16(float* dst, const float* src) {
    unsigned s = (unsigned)__cvta_generic_to_shared(dst);
    asm volatile("cp.async.cg.shared.global [%0], [%1], 16;" :: "r"(s), "l"(src));
}

// ======================= Kernel 1: couplings ============================
__global__ void __launch_bounds__(T1, 1)
k_couplings(const float* __restrict__ X, const float* __restrict__ Y,
            const float* __restrict__ G, const float* __restrict__ Bln,
            const float* __restrict__ W, const float* __restrict__ Blin,
            float* __restrict__ out)
{
    extern __shared__ float sm[];
    const int t = threadIdx.x;
    const int b = blockIdx.x;
    const float* xb = X + (size_t)b * (Mdim*Hdim);
    const float* yb = Y + (size_t)b * (Mdim*Hdim);

    const int ks = t & 7;               // k-slice 0..7
    const int tile = t >> 3;            // 0..35
    const int m0 = (tile / 6) * 6;
    const int n0 = (tile % 6) * 6;
    const int sr = t >> 2;              // stats row 0..71 (x rows then y rows)
    const int sl = t & 3;               // stats slice 0..3

    // ---- issue chunk 0 loads ----
    {
        float* xd = sm + OXS;
        float* yd = sm + OYS;
        #pragma unroll
        for (int rr = 0; rr < 8; ++rr) {
            int idx = t + T1*rr;                 // 0..2303
            bool isx = idx < 1152;
            int li = isx ? idx : idx - 1152;
            int row = li >> 5, c4 = li & 31;
            const float* src = (isx ? xb : yb) + row*Hdim + c4*4;
            float* dst = (isx ? xd : yd) + row*132 + c4*4;
            cp16(dst, src);
        }
        asm volatile("cp.async.commit_group;");
    }

    // ---- g*w vector + warp partials for Sgw, Sbw (overlaps DRAM) ----
    {
        float sgw = 0.f, sbw = 0.f;
        for (int h = t; h < Hdim; h += T1) {
            float wv = W[h];
            float gv = G[h]*wv;
            sm[OGW + h] = gv;
            sgw += gv;
            sbw += Bln[h]*wv;
        }
        #pragma unroll
        for (int o = 16; o > 0; o >>= 1) {
            sgw += __shfl_down_sync(0xffffffffu, sgw, o);
            sbw += __shfl_down_sync(0xffffffffu, sbw, o);
        }
        if ((t & 31) == 0) {
            sm[OWP + (t>>5)*2 + 0] = sgw;
            sm[OWP + (t>>5)*2 + 1] = sbw;
        }
    }

    unsigned long long acc[36];
    #pragma unroll
    for (int e = 0; e < 36; ++e) acc[e] = 0ULL;
    float sx = 0.f, sxx = 0.f, sxg = 0.f;

    #pragma unroll 1
    for (int ch = 0; ch < CHUNKS; ++ch) {
        if (ch + 1 < CHUNKS) {
            const int buf = (ch+1) & 1;
            float* xd = sm + OXS + buf*4752;
            float* yd = sm + OYS + buf*4752;
            const int koff = (ch+1)*KC;
            #pragma unroll
            for (int rr = 0; rr < 8; ++rr) {
                int idx = t + T1*rr;
                bool isx = idx < 1152;
                int li = isx ? idx : idx - 1152;
                int row = li >> 5, c4 = li & 31;
                const float* src = (isx ? xb : yb) + row*Hdim + koff + c4*4;
                float* dst = (isx ? xd : yd) + row*132 + c4*4;
                cp16(dst, src);
            }
            asm volatile("cp.async.commit_group;");
            asm volatile("cp.async.wait_group 1;");
        } else {
            asm volatile("cp.async.wait_group 0;");
        }
        __syncthreads();

        const int buf = ch & 1;
        const float* xsb = sm + OXS + buf*4752;
        const float* ysb = sm + OYS + buf*4752;

        // ---- GEMM: 6x6 tile, f32x2 packed FMA ----
        #pragma unroll
        for (int q = 0; q < 4; ++q) {
            const int j4 = (ks + q*8) * 4;       // float offset of float4
            ulonglong2 xv[6], yv[6];
            #pragma unroll
            for (int i = 0; i < 6; ++i)
                xv[i] = *reinterpret_cast<const ulonglong2*>(xsb + (m0+i)*132 + j4);
            #pragma unroll
            for (int j = 0; j < 6; ++j)
                yv[j] = *reinterpret_cast<const ulonglong2*>(ysb + (n0+j)*132 + j4);
            #pragma unroll
            for (int i = 0; i < 6; ++i)
                #pragma unroll
                for (int j = 0; j < 6; ++j) {
                    fma2(acc[i*6+j], xv[i].x, yv[j].x);
                    fma2(acc[i*6+j], xv[i].y, yv[j].y);
                }
        }

        // ---- per-row stats ----
        const float* rowp = (sr < 36) ? (xsb + sr*132) : (ysb + (sr-36)*132);
        const float* gwc = sm + OGW + ch*KC;
        #pragma unroll 8
        for (int qq = 0; qq < 32; ++qq) {
            int k = sl + qq*4;
            float vv = rowp[k];
            sx += vv;
            sxx = fmaf(vv, vv, sxx);
            sxg = fmaf(vv, gwc[k], sxg);
        }
        __syncthreads();
    }

    // ---- write stat partials ----
    sm[OST + (sr*4 + sl)*3 + 0] = sx;
    sm[OST + (sr*4 + sl)*3 + 1] = sxx;
    sm[OST + (sr*4 + sl)*3 + 2] = sxg;

    // ---- reduce GEMM accumulators across 8 k-slices (register only) ----
    float accf[36];
    #pragma unroll
    for (int e = 0; e < 36; ++e) {
        unsigned long long a = acc[e];
        float s = __uint_as_float((unsigned)a) + __uint_as_float((unsigned)(a >> 32));
        s += __shfl_down_sync(0xffffffffu, s, 4, 8);
        s += __shfl_down_sync(0xffffffffu, s, 2, 8);
        s += __shfl_down_sync(0xffffffffu, s, 1, 8);
        accf[e] = s;
    }
    __syncthreads();

    // ---- finalize per-row quantities ----
    if (t < 72) {
        float Sx = 0.f, Sxx = 0.f, Sxg = 0.f;
        #pragma unroll
        for (int s2 = 0; s2 < 4; ++s2) {
            Sx  += sm[OST + (t*4+s2)*3 + 0];
            Sxx += sm[OST + (t*4+s2)*3 + 1];
            Sxg += sm[OST + (t*4+s2)*3 + 2];
        }
        float Sgw = 0.f, Sbw = 0.f;
        #pragma unroll
        for (int ww = 0; ww < 9; ++ww) {
            Sgw += sm[OWP + ww*2 + 0];
            Sbw += sm[OWP + ww*2 + 1];
        }
        sm[ORN + t] = rsqrtf(Sxx);                      // 1/||row||
        float mu  = Sx * (1.f/768.f);
        float var = Sxx * (1.f/768.f) - mu*mu;
        float rsd = rsqrtf(var + 1e-5f);
        // LN -> Linear -> tanh collapsed; *10 = /REG
        sm[ODU + t] = tanhf((Sxg - mu*Sgw)*rsd + Sbw + Blin[0]) * 10.f;
    }
    __syncthreads();

    // ---- assemble couplings in smem ----
    if (ks == 0) {
        #pragma unroll
        for (int i = 0; i < 6; ++i) {
            float rx = sm[ORN + m0 + i];
            #pragma unroll
            for (int j = 0; j < 6; ++j)
                sm[OCS + (m0+i)*37 + (n0+j)] =
                    accf[i*6+j] * rx * sm[ORN + 36 + n0 + j] * 10.f;
        }
    }
    if (t < 36) {
        sm[OCS + t*37 + 36]  = sm[ODU + t];        // ax / REG
        sm[OCS + 36*37 + t]  = sm[ODU + 36 + t];   // ay / REG
    }
    if (t == 0) sm[OCS + 36*37 + 36] = -1000.f;    // alpha_both / REG
    __syncthreads();

    // ---- coalesced write of couplings into Z region of d_out ----
    float* ob = out + (size_t)b * NP1;
    for (int i = t; i < NP1; i += T1) ob[i] = sm[OCS + i];
}

// ======================= Kernel 2: Sinkhorn =============================
#define BPC 4
#define T2 160
#define NORMC (-4.27666611901605529f)   // -log(72)
#define LMD   (-0.69314718055994531f)   // log(36) - log(72)

__global__ void __launch_bounds__(T2)
k_sinkhorn(float* __restrict__ out, int B)
{
    __shared__ float c[BPC*NP1];
    __shared__ float u[BPC*37];
    __shared__ float v[BPC*37];
    __shared__ float tot[BPC];
    const int t = threadIdx.x;
    const int b0 = blockIdx.x * BPC;
    const int nb = min(BPC, B - b0);
    float* gbase = out + (size_t)b0 * NP1;
    const int nf = nb * NP1;
    for (int i = t; i < nf; i += T2) c[i] = gbase[i];
    if (t < BPC) tot[t] = 0.f;

    int lb = t / 37; if (lb > BPC-1) lb = BPC-1;
    const int m = t - (t/37)*37;
    const bool act = t < nb*37;
    float* cb = c + lb*NP1;
    float* ub = u + lb*37;
    float* vb = v + lb*37;
    const float lr = (m < 36) ? NORMC : LMD;   // log_mu == log_nu (M==N)
    if (act) { ub[m] = 0.f; vb[m] = 0.f; }
    __syncthreads();

    #pragma unroll 1
    for (int it = 0; it < 20; ++it) {
        if (act) {  // u-update over row m
            const float* crow = cb + m*37;
            float mx = -1e30f;
            #pragma unroll
            for (int n = 0; n < 37; ++n) mx = fmaxf(mx, crow[n] + vb[n]);
            float s = 0.f;
            #pragma unroll
            for (int n = 0; n < 37; ++n) s += __expf(crow[n] + vb[n] - mx);
            ub[m] = lr - (mx + __logf(s));
        }
        __syncthreads();
        if (act) {  // v-update over column m
            const float* ccol = cb + m;
            float mx = -1e30f;
            #pragma unroll
            for (int n = 0; n < 37; ++n) mx = fmaxf(mx, ccol[n*37] + ub[n]);
            float s = 0.f;
            #pragma unroll
            for (int n = 0; n < 37; ++n) s += __expf(ccol[n*37] + ub[n] - mx);
            vb[m] = lr - (mx + __logf(s));
        }
        __syncthreads();
    }

    // ---- Z + per-batch total; total = sum exp(Z)*c (REG/TEMP == 1) ----
    for (int lb2 = 0; lb2 < nb; ++lb2) {
        float part = 0.f;
        const float* cl = c + lb2*NP1;
        const float* ul = u + lb2*37;
        const float* vl = v + lb2*37;
        float* gl = gbase + (size_t)lb2*NP1;
        for (int i = t; i < NP1; i += T2) {
            int mm = i / 37;
            int nn = i - mm*37;
            float cc = cl[i];
            float z = cc + ul[mm] + vl[nn] - NORMC;
            gl[i] = z;
            if (mm < 36 && nn < 36) part += __expf(z) * cc;
        }
        atomicAdd(&tot[lb2], part);
    }
    __syncthreads();
    if (t < nb) out[(size_t)B*NP1 + b0 + t] = tot[t];
}

// ======================= launch =========================================
extern "C" void kernel_launch(void* const* d_in, const int* in_sizes, int n_in,
                              void* d_out, int out_size)
{
    const float* x  = (const float*)d_in[0];
    const float* y  = (const float*)d_in[1];
    const float* g  = (const float*)d_in[2];
    const float* bb = (const float*)d_in[3];
    const float* w  = (const float*)d_in[4];
    const float* bl = (const float*)d_in[5];
    const int B = in_sizes[0] / (Mdim * Hdim);
    float* out = (float*)d_out;

    cudaFuncSetAttribute(k_couplings,
                         cudaFuncAttributeMaxDynamicSharedMemorySize, SM1_BYTES);
    k_couplings<<<B, T1, SM1_BYTES>>>(x, y, g, bb, w, bl, out);
    k_sinkhorn<<<(B + BPC - 1)/BPC, T2>>>(out, B);
}

// round 2
// speedup vs baseline: 1.0530x; 1.0530x over previous
#include <cuda_runtime.h>
#include <cstdint>

#define Hdim 768
#define Mdim 36
#define KC 64
#define CHUNKS 12           // 768/64
#define T1 144
#define NP1 1369            // 37*37
#define STRIDE 68           // 64 + 4 pad (floats)
#define BUFS (72*STRIDE)    // 4896 floats per buffer

// ---------------- smem offsets for kernel 1 (in floats) ----------------
#define OXY 0               // 2 bufs * 72 rows * 68 = 9792
#define OGW 9792            // g*w vector: 768
#define OCS 10560           // couplings 1369
#define OST 11929           // stat partials 72*2*3 = 432
#define ORN 12361           // rsqrt row norms, 72
#define ODU 12433           // dustbin*10, 72
#define OWP 12505           // gw warp partials 144*2 = 288
#define SM1_FLOATS 12800
#define SM1_BYTES (SM1_FLOATS*4)

__device__ __forceinline__ void fma2(unsigned long long &d,
                                     unsigned long long a,
                                     unsigned long long b) {
    asm volatile("fma.rn.f32x2 %0, %1, %2, %0;" : "+l"(d) : "l"(a), "l"(b));
}

__device__ __forceinline__ void cp16(float* dst, const float* src) {
    unsigned s = (unsigned)__cvta_generic_to_shared(dst);
    asm volatile("cp.async.cg.shared.global [%0], [%1], 16;" :: "r"(s), "l"(src));
}

// load one 72x64 chunk (x rows 0-35, y rows 36-71) into buffer
__device__ __forceinline__ void load_chunk(float* buf, const float* xb,
                                           const float* yb, int koff, int t)
{
    #pragma unroll
    for (int rr = 0; rr < 8; ++rr) {
        int idx = t + T1*rr;              // 0..1151 (72 rows * 16 float4)
        int row = idx >> 4;
        int c4  = idx & 15;
        const float* src = (row < 36 ? xb + row*Hdim
                                     : yb + (row-36)*Hdim) + koff + c4*4;
        cp16(buf + row*STRIDE + c4*4, src);
    }
    asm volatile("cp.async.commit_group;");
}

// ======================= Kernel 1: couplings ============================
__global__ void __launch_bounds__(T1, 3)
k_couplings(const float* __restrict__ X, const float* __restrict__ Y,
            const float* __restrict__ G, const float* __restrict__ Bln,
            const float* __restrict__ W, const float* __restrict__ Blin,
            float* __restrict__ out)
{
    extern __shared__ float sm[];
    const int t = threadIdx.x;
    const int b = blockIdx.x;
    const float* xb = X + (size_t)b * (Mdim*Hdim);
    const float* yb = Y + (size_t)b * (Mdim*Hdim);

    const int ks = t & 3;               // k-slice 0..3
    const int tile = t >> 2;            // 0..35
    const int m0 = (tile / 6) * 6;
    const int n0 = (tile % 6) * 6;
    const int sr = t >> 1;              // stats row 0..71
    const int sl = t & 1;               // stats slice 0..1

    load_chunk(sm + OXY, xb, yb, 0, t);

    // ---- g*w vector + per-thread partials for Sgw, Sbw ----
    {
        float sgw = 0.f, sbw = 0.f;
        for (int h = t; h < Hdim; h += T1) {
            float wv = W[h];
            float gv = G[h]*wv;
            sm[OGW + h] = gv;
            sgw += gv;
            sbw += Bln[h]*wv;
        }
        sm[OWP + t*2 + 0] = sgw;
        sm[OWP + t*2 + 1] = sbw;
    }

    unsigned long long acc[36];
    #pragma unroll
    for (int e = 0; e < 36; ++e) acc[e] = 0ULL;
    float sx = 0.f, sxx = 0.f, sxg = 0.f;

    #pragma unroll 1
    for (int ch = 0; ch < CHUNKS; ++ch) {
        if (ch + 1 < CHUNKS) {
            load_chunk(sm + OXY + ((ch+1)&1)*BUFS, xb, yb, (ch+1)*KC, t);
            asm volatile("cp.async.wait_group 1;");
        } else {
            asm volatile("cp.async.wait_group 0;");
        }
        __syncthreads();

        const float* xy = sm + OXY + (ch&1)*BUFS;

        // ---- GEMM: 6x6 tile, f32x2 packed FMA ----
        #pragma unroll
        for (int q = 0; q < 4; ++q) {
            const int j4 = (ks + q*4) * 4;       // float offset of float4
            ulonglong2 xv[6], yv[6];
            #pragma unroll
            for (int i = 0; i < 6; ++i)
                xv[i] = *reinterpret_cast<const ulonglong2*>(xy + (m0+i)*STRIDE + j4);
            #pragma unroll
            for (int j = 0; j < 6; ++j)
                yv[j] = *reinterpret_cast<const ulonglong2*>(xy + (36+n0+j)*STRIDE + j4);
            #pragma unroll
            for (int i = 0; i < 6; ++i)
                #pragma unroll
                for (int j = 0; j < 6; ++j) {
                    fma2(acc[i*6+j], xv[i].x, yv[j].x);
                    fma2(acc[i*6+j], xv[i].y, yv[j].y);
                }
        }

        // ---- per-row stats ----
        const float* rowp = xy + sr*STRIDE;
        const float* gwc = sm + OGW + ch*KC;
        #pragma unroll 8
        for (int qq = 0; qq < 32; ++qq) {
            int k = sl + qq*2;
            float vv = rowp[k];
            sx += vv;
            sxx = fmaf(vv, vv, sxx);
            sxg = fmaf(vv, gwc[k], sxg);
        }
        __syncthreads();
    }

    // ---- write stat partials ----
    sm[OST + (sr*2 + sl)*3 + 0] = sx;
    sm[OST + (sr*2 + sl)*3 + 1] = sxx;
    sm[OST + (sr*2 + sl)*3 + 2] = sxg;

    // ---- reduce GEMM accumulators across 4 k-slices (register only) ----
    float accf[36];
    #pragma unroll
    for (int e = 0; e < 36; ++e) {
        unsigned long long a = acc[e];
        float s = __uint_as_float((unsigned)a) + __uint_as_float((unsigned)(a >> 32));
        s += __shfl_down_sync(0xffffffffu, s, 2, 4);
        s += __shfl_down_sync(0xffffffffu, s, 1, 4);
        accf[e] = s;
    }
    __syncthreads();

    // ---- finalize per-row quantities ----
    if (t < 72) {
        float Sx = 0.f, Sxx = 0.f, Sxg = 0.f;
        #pragma unroll
        for (int s2 = 0; s2 < 2; ++s2) {
            Sx  += sm[OST + (t*2+s2)*3 + 0];
            Sxx += sm[OST + (t*2+s2)*3 + 1];
            Sxg += sm[OST + (t*2+s2)*3 + 2];
        }
        float Sgw = 0.f, Sbw = 0.f;
        for (int j = 0; j < T1; ++j) {
            Sgw += sm[OWP + j*2 + 0];
            Sbw += sm[OWP + j*2 + 1];
        }
        sm[ORN + t] = rsqrtf(Sxx);                      // 1/||row||
        float mu  = Sx * (1.f/768.f);
        float var = Sxx * (1.f/768.f) - mu*mu;
        float rsd = rsqrtf(var + 1e-5f);
        sm[ODU + t] = tanhf((Sxg - mu*Sgw)*rsd + Sbw + Blin[0]) * 10.f;
    }
    __syncthreads();

    // ---- assemble couplings in smem ----
    if (ks == 0) {
        #pragma unroll
        for (int i = 0; i < 6; ++i) {
            float rx = sm[ORN + m0 + i];
            #pragma unroll
            for (int j = 0; j < 6; ++j)
                sm[OCS + (m0+i)*37 + (n0+j)] =
                    accf[i*6+j] * rx * sm[ORN + 36 + n0 + j] * 10.f;
        }
    }
    if (t < 36) {
        sm[OCS + t*37 + 36]  = sm[ODU + t];        // ax / REG
        sm[OCS + 36*37 + t]  = sm[ODU + 36 + t];   // ay / REG
    }
    if (t == 0) sm[OCS + 36*37 + 36] = -1000.f;    // alpha_both / REG
    __syncthreads();

    float* ob = out + (size_t)b * NP1;
    for (int i = t; i < NP1; i += T1) ob[i] = sm[OCS + i];
}

// ======================= Kernel 2: Sinkhorn =============================
#define BPC 4
#define T2 160
#define NORMC (-4.27666611901605529f)   // -log(72)
#define LMD   (-0.69314718055994531f)   // log(36) - log(72)

__global__ void __launch_bounds__(T2)
k_sinkhorn(float* __restrict__ out, int B)
{
    __shared__ float c[BPC*NP1];
    __shared__ float ec[BPC*NP1];
    __shared__ float u[BPC*37], v[BPC*37];
    __shared__ float eu[BPC*37], ev[BPC*37];
    __shared__ float tot[BPC];
    const int t = threadIdx.x;
    const int b0 = blockIdx.x * BPC;
    const int nb = min(BPC, B - b0);
    float* gbase = out + (size_t)b0 * NP1;
    const int nf = nb * NP1;
    for (int i = t; i < nf; i += T2) {
        float cc = gbase[i];
        c[i] = cc;
        ec[i] = __expf(cc);
    }
    if (t < BPC) tot[t] = 0.f;

    int lb = t / 37; if (lb > BPC-1) lb = BPC-1;
    const int m = t - (t/37)*37;
    const bool act = t < nb*37;
    float* ecb = ec + lb*NP1;
    const float lr = (m < 36) ? NORMC : LMD;   // log_mu == log_nu (M==N)
    if (act) { u[lb*37+m]=0.f; v[lb*37+m]=0.f; eu[lb*37+m]=1.f; ev[lb*37+m]=1.f; }
    __syncthreads();

    #pragma unroll 1
    for (int it = 0; it < 20; ++it) {
        if (act) {  // u-update over row m:  u = lr - log(sum ec_row * ev)
            const float* er  = ecb + m*37;
            const float* evb = ev + lb*37;
            float s0=0.f, s1=0.f, s2=0.f, s3=0.f;
            #pragma unroll
            for (int n = 0; n < 36; n += 4) {
                s0 = fmaf(er[n+0], evb[n+0], s0);
                s1 = fmaf(er[n+1], evb[n+1], s1);
                s2 = fmaf(er[n+2], evb[n+2], s2);
                s3 = fmaf(er[n+3], evb[n+3], s3);
            }
            s0 = fmaf(er[36], evb[36], s0);
            float uu = lr - __logf((s0+s1)+(s2+s3));
            u[lb*37+m] = uu;
            eu[lb*37+m] = __expf(uu);
        }
        __syncthreads();
        if (act) {  // v-update over column m
            const float* ecc = ecb + m;
            const float* eub = eu + lb*37;
            float s0=0.f, s1=0.f, s2=0.f, s3=0.f;
            #pragma unroll
            for (int n = 0; n < 36; n += 4) {
                s0 = fmaf(ecc[(n+0)*37], eub[n+0], s0);
                s1 = fmaf(ecc[(n+1)*37], eub[n+1], s1);
                s2 = fmaf(ecc[(n+2)*37], eub[n+2], s2);
                s3 = fmaf(ecc[(n+3)*37], eub[n+3], s3);
            }
            s0 = fmaf(ecc[36*37], eub[36], s0);
            float vv = lr - __logf((s0+s1)+(s2+s3));
            v[lb*37+m] = vv;
            ev[lb*37+m] = __expf(vv);
        }
        __syncthreads();
    }

    // ---- Z + per-batch total; exp(Z) = 72 * ec * eu * ev ----
    for (int lb2 = 0; lb2 < nb; ++lb2) {
        float part = 0.f;
        const float* cl  = c  + lb2*NP1;
        const float* ecl = ec + lb2*NP1;
        const float* ul  = u  + lb2*37;
        const float* vl  = v  + lb2*37;
        const float* eul = eu + lb2*37;
        const float* evl = ev + lb2*37;
        float* gl = gbase + (size_t)lb2*NP1;
        for (int i = t; i < NP1; i += T2) {
            int mm = i / 37;
            int nn = i - mm*37;
            float cc = cl[i];
            gl[i] = cc + ul[mm] + vl[nn] - NORMC;
            if (mm < 36 && nn < 36)
                part += ecl[i] * eul[mm] * evl[nn] * cc;
        }
        atomicAdd(&tot[lb2], part * 72.f);
    }
    __syncthreads();
    if (t < nb) out[(size_t)B*NP1 + b0 + t] = tot[t];
}

// ======================= launch =========================================
extern "C" void kernel_launch(void* const* d_in, const int* in_sizes, int n_in,
                              void* d_out, int out_size)
{
    const float* x  = (const float*)d_in[0];
    const float* y  = (const float*)d_in[1];
    const float* g  = (const float*)d_in[2];
    const float* bb = (const float*)d_in[3];
    const float* w  = (const float*)d_in[4];
    const float* bl = (const float*)d_in[5];
    const int B = in_sizes[0] / (Mdim * Hdim);
    float* out = (float*)d_out;

    cudaFuncSetAttribute(k_couplings,
                         cudaFuncAttributeMaxDynamicSharedMemorySize, SM1_BYTES);
    k_couplings<<<B, T1, SM1_BYTES>>>(x, y, g, bb, w, bl, out);
    k_sinkhorn<<<(B + BPC - 1)/BPC, T2>>>(out, B);
}